// round 5
// baseline (speedup 1.0000x reference)
#include <cuda_runtime.h>
#include <math.h>

#define NN 8192
#define EE 524288
#define ET (EE + NN)

// ---------------- scratch (device globals; no allocation allowed) ----------
__device__ __align__(16) float g_x  [NN * 64];   // node features
__device__ __align__(16) float g_t0 [NN * 64];   // xl  / A (= x @ We1_top)
__device__ __align__(16) float g_t1 [NN * 64];   // xr  / B (= x @ We1_bot + be1)
__device__             float g_p   [ET * 4];     // per-edge unnormalized attn
__device__             float g_den [NN * 4];     // softmax denominators
__device__ __align__(16) float g_agg[NN * 64];   // attention aggregation

// FMA one weight row (64 wide) into a 64-accumulator array, vectorized smem reads
__device__ __forceinline__ void fma_row(float (&a)[64], float v, const float* wrow) {
    const float4* w = reinterpret_cast<const float4*>(wrow);
#pragma unroll
    for (int jj = 0; jj < 16; jj++) {
        float4 wv = w[jj];
        a[jj * 4 + 0] += v * wv.x;
        a[jj * 4 + 1] += v * wv.y;
        a[jj * 4 + 2] += v * wv.z;
        a[jj * 4 + 3] += v * wv.w;
    }
}

// ---------------- input MLP: g_x = relu(x @ W1 + b1) ------------------------
__global__ void k_in_mlp(const float* __restrict__ x,
                         const float* __restrict__ W1,
                         const float* __restrict__ b1) {
    __shared__ float sW[12 * 64];
    __shared__ float sb[64];
    for (int i = threadIdx.x; i < 12 * 64; i += blockDim.x) sW[i] = W1[i];
    if (threadIdx.x < 64) sb[threadIdx.x] = b1[threadIdx.x];
    __syncthreads();
    int r = blockIdx.x * blockDim.x + threadIdx.x;
    if (r >= NN) return;

    float xi[12];
#pragma unroll
    for (int k = 0; k < 12; k++) xi[k] = x[r * 12 + k];

    float a[64];
#pragma unroll
    for (int j = 0; j < 64; j++) a[j] = sb[j];
#pragma unroll
    for (int k = 0; k < 12; k++) fma_row(a, xi[k], &sW[k * 64]);

    float4* o = reinterpret_cast<float4*>(&g_x[r * 64]);
#pragma unroll
    for (int jj = 0; jj < 16; jj++)
        o[jj] = make_float4(fmaxf(a[jj * 4 + 0], 0.f), fmaxf(a[jj * 4 + 1], 0.f),
                            fmaxf(a[jj * 4 + 2], 0.f), fmaxf(a[jj * 4 + 3], 0.f));
}

// ---------------- residual layer: g_x = g_x + relu(g_x @ W + b) -------------
__global__ void k_resid(const float* __restrict__ W, const float* __restrict__ b) {
    __shared__ float sW[64 * 64];
    __shared__ float sb[64];
    for (int i = threadIdx.x; i < 4096; i += blockDim.x) sW[i] = W[i];
    if (threadIdx.x < 64) sb[threadIdx.x] = b[threadIdx.x];
    __syncthreads();
    int r = blockIdx.x * blockDim.x + threadIdx.x;
    if (r >= NN) return;

    const float4* xr4 = reinterpret_cast<const float4*>(&g_x[r * 64]);
    float a[64];
#pragma unroll
    for (int j = 0; j < 64; j++) a[j] = sb[j];
#pragma unroll 1
    for (int i = 0; i < 16; i++) {
        float4 v = xr4[i];
        fma_row(a, v.x, &sW[(4 * i + 0) * 64]);
        fma_row(a, v.y, &sW[(4 * i + 1) * 64]);
        fma_row(a, v.z, &sW[(4 * i + 2) * 64]);
        fma_row(a, v.w, &sW[(4 * i + 3) * 64]);
    }
    float4* o = reinterpret_cast<float4*>(&g_x[r * 64]);
#pragma unroll
    for (int jj = 0; jj < 16; jj++) {
        float4 v = xr4[jj];
        o[jj] = make_float4(v.x + fmaxf(a[jj * 4 + 0], 0.f),
                            v.y + fmaxf(a[jj * 4 + 1], 0.f),
                            v.z + fmaxf(a[jj * 4 + 2], 0.f),
                            v.w + fmaxf(a[jj * 4 + 3], 0.f));
    }
}

// ---------------- dual linear: g_t0 = x@Wa + ba, g_t1 = x@Wb + bb -----------
// ba may be nullptr (treated as zero)
__global__ void k_lin2(const float* __restrict__ Wa, const float* __restrict__ ba,
                       const float* __restrict__ Wb, const float* __restrict__ bb) {
    __shared__ float sWa[4096], sWb[4096];
    __shared__ float sba[64], sbb[64];
    for (int i = threadIdx.x; i < 4096; i += blockDim.x) { sWa[i] = Wa[i]; sWb[i] = Wb[i]; }
    if (threadIdx.x < 64) {
        sba[threadIdx.x] = ba ? ba[threadIdx.x] : 0.f;
        sbb[threadIdx.x] = bb[threadIdx.x];
    }
    __syncthreads();
    int r = blockIdx.x * blockDim.x + threadIdx.x;
    if (r >= NN) return;

    const float4* xr4 = reinterpret_cast<const float4*>(&g_x[r * 64]);
    {
        float a[64];
#pragma unroll
        for (int j = 0; j < 64; j++) a[j] = sba[j];
#pragma unroll 1
        for (int i = 0; i < 16; i++) {
            float4 v = xr4[i];
            fma_row(a, v.x, &sWa[(4 * i + 0) * 64]);
            fma_row(a, v.y, &sWa[(4 * i + 1) * 64]);
            fma_row(a, v.z, &sWa[(4 * i + 2) * 64]);
            fma_row(a, v.w, &sWa[(4 * i + 3) * 64]);
        }
        float4* o = reinterpret_cast<float4*>(&g_t0[r * 64]);
#pragma unroll
        for (int jj = 0; jj < 16; jj++)
            o[jj] = make_float4(a[jj * 4 + 0], a[jj * 4 + 1], a[jj * 4 + 2], a[jj * 4 + 3]);
    }
    {
        float a[64];
#pragma unroll
        for (int j = 0; j < 64; j++) a[j] = sbb[j];
#pragma unroll 1
        for (int i = 0; i < 16; i++) {
            float4 v = xr4[i];
            fma_row(a, v.x, &sWb[(4 * i + 0) * 64]);
            fma_row(a, v.y, &sWb[(4 * i + 1) * 64]);
            fma_row(a, v.z, &sWb[(4 * i + 2) * 64]);
            fma_row(a, v.w, &sWb[(4 * i + 3) * 64]);
        }
        float4* o = reinterpret_cast<float4*>(&g_t1[r * 64]);
#pragma unroll
        for (int jj = 0; jj < 16; jj++)
            o[jj] = make_float4(a[jj * 4 + 0], a[jj * 4 + 1], a[jj * 4 + 2], a[jj * 4 + 3]);
    }
}

// ---------------- zero attention scratch ------------------------------------
__global__ void k_zero() {
    int i = blockIdx.x * blockDim.x + threadIdx.x;
    if (i < NN * 4)  g_den[i] = 0.f;
    if (i < NN * 64) g_agg[i] = 0.f;
}

// ---------------- GAT edge pass 1: logits -> exp -> denominator -------------
__global__ void k_edge_att(const int* __restrict__ src, const int* __restrict__ dst,
                           const float* __restrict__ att) {
    __shared__ float satt[64];
    if (threadIdx.x < 64) satt[threadIdx.x] = att[threadIdx.x];
    __syncthreads();
    int e = blockIdx.x * blockDim.x + threadIdx.x;
    if (e >= ET) return;
    int s, d;
    if (e < EE) { s = src[e]; d = dst[e]; } else { s = e - EE; d = s; }

    const float4* xl = reinterpret_cast<const float4*>(&g_t0[s * 64]);
    const float4* xr = reinterpret_cast<const float4*>(&g_t1[d * 64]);
    float lg[4] = {0.f, 0.f, 0.f, 0.f};
#pragma unroll
    for (int i = 0; i < 16; i++) {
        float4 a = xl[i], b = xr[i];
        float v0 = a.x + b.x; v0 = v0 > 0.f ? v0 : 0.2f * v0;
        float v1 = a.y + b.y; v1 = v1 > 0.f ? v1 : 0.2f * v1;
        float v2 = a.z + b.z; v2 = v2 > 0.f ? v2 : 0.2f * v2;
        float v3 = a.w + b.w; v3 = v3 > 0.f ? v3 : 0.2f * v3;
        lg[i >> 2] += v0 * satt[i * 4 + 0] + v1 * satt[i * 4 + 1]
                    + v2 * satt[i * 4 + 2] + v3 * satt[i * 4 + 3];
    }
#pragma unroll
    for (int h = 0; h < 4; h++) {
        float p = expf(lg[h]);           // softmax is shift-invariant: max-sub omitted
        g_p[e * 4 + h] = p;
        atomicAdd(&g_den[d * 4 + h], p);
    }
}

// ---------------- GAT edge pass 2: aggregate alpha * xl[src] into g_agg -----
__global__ void k_edge_agg(const int* __restrict__ src, const int* __restrict__ dst) {
    int e = blockIdx.x * blockDim.x + threadIdx.x;
    if (e >= ET) return;
    int s, d;
    if (e < EE) { s = src[e]; d = dst[e]; } else { s = e - EE; d = s; }

    float al[4];
#pragma unroll
    for (int h = 0; h < 4; h++) al[h] = g_p[e * 4 + h] / g_den[d * 4 + h];

    const float4* xl = reinterpret_cast<const float4*>(&g_t0[s * 64]);
    float* o = &g_agg[d * 64];
#pragma unroll
    for (int i = 0; i < 16; i++) {
        float4 a = xl[i];
        float v = al[i >> 2];
        atomicAdd(o + 4 * i + 0, v * a.x);
        atomicAdd(o + 4 * i + 1, v * a.y);
        atomicAdd(o + 4 * i + 2, v * a.z);
        atomicAdd(o + 4 * i + 3, v * a.w);
    }
}

// ---------------- finish GAT layer: x += agg + bo ---------------------------
__global__ void k_add_agg(const float* __restrict__ bo) {
    int i = blockIdx.x * blockDim.x + threadIdx.x;
    if (i < NN * 64) g_x[i] += g_agg[i] + bo[i & 63];
}

// ---------------- edge MLP + scatter into dense NxN output ------------------
// h1 = A[src] + B[dst]; h2 = relu(h1 @ We2 + be2); v = sigmoid(h2 . We3 + be3)
__global__ void k_edge_mlp(const int* __restrict__ src, const int* __restrict__ dst,
                           const float* __restrict__ We2, const float* __restrict__ be2,
                           const float* __restrict__ We3, const float* __restrict__ be3,
                           float* __restrict__ out) {
    __shared__ float sW[64 * 64];
    __shared__ float sb2[64], sw3[64];
    __shared__ float sb3;
    for (int i = threadIdx.x; i < 4096; i += blockDim.x) sW[i] = We2[i];
    if (threadIdx.x < 64) { sb2[threadIdx.x] = be2[threadIdx.x]; sw3[threadIdx.x] = We3[threadIdx.x]; }
    if (threadIdx.x == 0) sb3 = be3[0];
    __syncthreads();
    int e = blockIdx.x * blockDim.x + threadIdx.x;
    if (e >= EE) return;
    int s = src[e], d = dst[e];

    float acc[64];
#pragma unroll
    for (int j = 0; j < 64; j++) acc[j] = sb2[j];

    const float4* A = reinterpret_cast<const float4*>(&g_t0[s * 64]);
    const float4* B = reinterpret_cast<const float4*>(&g_t1[d * 64]);
#pragma unroll 1
    for (int i = 0; i < 16; i++) {
        float4 av = A[i], bv = B[i];
        fma_row(acc, av.x + bv.x, &sW[(4 * i + 0) * 64]);
        fma_row(acc, av.y + bv.y, &sW[(4 * i + 1) * 64]);
        fma_row(acc, av.z + bv.z, &sW[(4 * i + 2) * 64]);
        fma_row(acc, av.w + bv.w, &sW[(4 * i + 3) * 64]);
    }
    float t = sb3;
#pragma unroll
    for (int j = 0; j < 64; j++) t += fmaxf(acc[j], 0.f) * sw3[j];
    float v = 1.f / (1.f + expf(-t));
    out[(size_t)s * NN + d] = v;
}

// ---------------------------------------------------------------------------
extern "C" void kernel_launch(void* const* d_in, const int* in_sizes, int n_in,
                              void* d_out, int out_size) {
    const float* x    = (const float*)d_in[0];
    const float* W1   = (const float*)d_in[1];
    const float* b1   = (const float*)d_in[2];
    const float* W2   = (const float*)d_in[3];
    const float* b2   = (const float*)d_in[4];
    const float* Wl1  = (const float*)d_in[5];
    const float* bl1  = (const float*)d_in[6];
    const float* Wr1  = (const float*)d_in[7];
    const float* br1  = (const float*)d_in[8];
    const float* att1 = (const float*)d_in[9];
    const float* bo1  = (const float*)d_in[10];
    const float* W4   = (const float*)d_in[11];
    const float* b4   = (const float*)d_in[12];
    const float* Wl2  = (const float*)d_in[13];
    const float* bl2  = (const float*)d_in[14];
    const float* Wr2  = (const float*)d_in[15];
    const float* br2  = (const float*)d_in[16];
    const float* att2 = (const float*)d_in[17];
    const float* bo2  = (const float*)d_in[18];
    const float* W5   = (const float*)d_in[19];
    const float* b5   = (const float*)d_in[20];
    const float* We1  = (const float*)d_in[21];
    const float* be1  = (const float*)d_in[22];
    const float* We2  = (const float*)d_in[23];
    const float* be2  = (const float*)d_in[24];
    const float* We3  = (const float*)d_in[25];
    const float* be3  = (const float*)d_in[26];
    const int*   src  = (const int*)d_in[27];
    const int*   dst  = (const int*)d_in[28];
    float* out = (float*)d_out;

    const int NB128 = NN / 128;                  // 64 blocks, thread-per-row
    const int EB    = (ET + 255) / 256;          // edge blocks
    const int ZB    = (NN * 64) / 256;           // elementwise blocks

    cudaMemsetAsync(d_out, 0, (size_t)NN * NN * sizeof(float));

    k_in_mlp<<<NB128, 128>>>(x, W1, b1);
    k_resid<<<NB128, 128>>>(W2, b2);

    // GAT layer 1
    k_lin2<<<NB128, 128>>>(Wl1, bl1, Wr1, br1);
    k_zero<<<ZB, 256>>>();
    k_edge_att<<<EB, 256>>>(src, dst, att1);
    k_edge_agg<<<EB, 256>>>(src, dst);
    k_add_agg<<<ZB, 256>>>(bo1);

    k_resid<<<NB128, 128>>>(W4, b4);

    // GAT layer 2
    k_lin2<<<NB128, 128>>>(Wl2, bl2, Wr2, br2);
    k_zero<<<ZB, 256>>>();
    k_edge_att<<<EB, 256>>>(src, dst, att2);
    k_edge_agg<<<EB, 256>>>(src, dst);
    k_add_agg<<<ZB, 256>>>(bo2);

    k_resid<<<NB128, 128>>>(W5, b5);

    // per-edge MLP: precompute per-node halves of the first linear layer
    k_lin2<<<NB128, 128>>>(We1, nullptr, We1 + 64 * 64, be1);
    k_edge_mlp<<<(EE + 255) / 256, 256>>>(src, dst, We2, be2, We3, be3, out);
}

// round 10
// speedup vs baseline: 1.6712x; 1.6712x over previous
#include <cuda_runtime.h>
#include <math.h>

#define NN 8192
#define EE 524288
#define ET (EE + NN)

// ---------------- scratch (device globals; no allocation allowed) ----------
__device__ __align__(16) float g_x  [NN * 64];   // node features
__device__ __align__(16) float g_t0 [NN * 64];   // xl  / A (= x @ We1_top)
__device__ __align__(16) float g_t1 [NN * 64];   // xr  / B (= x @ We1_bot + be1)
__device__             float g_p   [ET * 4];     // per-edge unnormalized attn
// CSR-by-dst (rebuilt every launch; graph-replay safe)
__device__ int g_cnt [NN];        // in-degree histogram
__device__ int g_rp  [NN + 1];    // row pointers
__device__ int g_fill[NN];        // scatter cursors
__device__ int g_cs  [EE];        // CSR: src node per slot
__device__ int g_ce  [EE];        // CSR: original edge id per slot

// FMA one weight row (64 wide) into a 64-accumulator array, vectorized smem reads
__device__ __forceinline__ void fma_row(float (&a)[64], float v, const float* wrow) {
    const float4* w = reinterpret_cast<const float4*>(wrow);
#pragma unroll
    for (int jj = 0; jj < 16; jj++) {
        float4 wv = w[jj];
        a[jj * 4 + 0] += v * wv.x;
        a[jj * 4 + 1] += v * wv.y;
        a[jj * 4 + 2] += v * wv.z;
        a[jj * 4 + 3] += v * wv.w;
    }
}

// ---- packed f32x2 helpers --------------------------------------------------
__device__ __forceinline__ unsigned long long pack2(float lo, float hi) {
    unsigned long long r;
    asm("mov.b64 %0, {%1, %2};" : "=l"(r) : "f"(lo), "f"(hi));
    return r;
}
__device__ __forceinline__ void unpack2(unsigned long long v, float& lo, float& hi) {
    asm("mov.b64 {%0, %1}, %2;" : "=f"(lo), "=f"(hi) : "l"(v));
}
__device__ __forceinline__ void fma2(unsigned long long& acc, unsigned long long a,
                                     unsigned long long b) {
    asm("fma.rn.f32x2 %0, %1, %2, %0;" : "+l"(acc) : "l"(a), "l"(b));
}

// ---------------- input MLP: g_x = relu(x @ W1 + b1) ------------------------
__global__ void k_in_mlp(const float* __restrict__ x,
                         const float* __restrict__ W1,
                         const float* __restrict__ b1) {
    __shared__ __align__(16) float sW[12 * 64];
    __shared__ float sb[64];
    for (int i = threadIdx.x; i < 12 * 64; i += blockDim.x) sW[i] = W1[i];
    if (threadIdx.x < 64) sb[threadIdx.x] = b1[threadIdx.x];
    __syncthreads();
    int r = blockIdx.x * blockDim.x + threadIdx.x;
    if (r >= NN) return;

    float xi[12];
#pragma unroll
    for (int k = 0; k < 12; k++) xi[k] = x[r * 12 + k];

    float a[64];
#pragma unroll
    for (int j = 0; j < 64; j++) a[j] = sb[j];
#pragma unroll
    for (int k = 0; k < 12; k++) fma_row(a, xi[k], &sW[k * 64]);

    float4* o = reinterpret_cast<float4*>(&g_x[r * 64]);
#pragma unroll
    for (int jj = 0; jj < 16; jj++)
        o[jj] = make_float4(fmaxf(a[jj * 4 + 0], 0.f), fmaxf(a[jj * 4 + 1], 0.f),
                            fmaxf(a[jj * 4 + 2], 0.f), fmaxf(a[jj * 4 + 3], 0.f));
}

// ---------------- residual layer: g_x = g_x + relu(g_x @ W + b) -------------
__global__ void k_resid(const float* __restrict__ W, const float* __restrict__ b) {
    __shared__ __align__(16) float sW[64 * 64];
    __shared__ float sb[64];
    for (int i = threadIdx.x; i < 4096; i += blockDim.x) sW[i] = W[i];
    if (threadIdx.x < 64) sb[threadIdx.x] = b[threadIdx.x];
    __syncthreads();
    int r = blockIdx.x * blockDim.x + threadIdx.x;
    if (r >= NN) return;

    const float4* xr4 = reinterpret_cast<const float4*>(&g_x[r * 64]);
    float a[64];
#pragma unroll
    for (int j = 0; j < 64; j++) a[j] = sb[j];
#pragma unroll 1
    for (int i = 0; i < 16; i++) {
        float4 v = xr4[i];
        fma_row(a, v.x, &sW[(4 * i + 0) * 64]);
        fma_row(a, v.y, &sW[(4 * i + 1) * 64]);
        fma_row(a, v.z, &sW[(4 * i + 2) * 64]);
        fma_row(a, v.w, &sW[(4 * i + 3) * 64]);
    }
    float4* o = reinterpret_cast<float4*>(&g_x[r * 64]);
#pragma unroll
    for (int jj = 0; jj < 16; jj++) {
        float4 v = xr4[jj];
        o[jj] = make_float4(v.x + fmaxf(a[jj * 4 + 0], 0.f),
                            v.y + fmaxf(a[jj * 4 + 1], 0.f),
                            v.z + fmaxf(a[jj * 4 + 2], 0.f),
                            v.w + fmaxf(a[jj * 4 + 3], 0.f));
    }
}

// ---------------- dual linear: g_t0 = x@Wa + ba, g_t1 = x@Wb + bb -----------
__global__ void k_lin2(const float* __restrict__ Wa, const float* __restrict__ ba,
                       const float* __restrict__ Wb, const float* __restrict__ bb) {
    __shared__ __align__(16) float sWa[4096], sWb[4096];
    __shared__ float sba[64], sbb[64];
    for (int i = threadIdx.x; i < 4096; i += blockDim.x) { sWa[i] = Wa[i]; sWb[i] = Wb[i]; }
    if (threadIdx.x < 64) {
        sba[threadIdx.x] = ba ? ba[threadIdx.x] : 0.f;
        sbb[threadIdx.x] = bb[threadIdx.x];
    }
    __syncthreads();
    int r = blockIdx.x * blockDim.x + threadIdx.x;
    if (r >= NN) return;

    const float4* xr4 = reinterpret_cast<const float4*>(&g_x[r * 64]);
    {
        float a[64];
#pragma unroll
        for (int j = 0; j < 64; j++) a[j] = sba[j];
#pragma unroll 1
        for (int i = 0; i < 16; i++) {
            float4 v = xr4[i];
            fma_row(a, v.x, &sWa[(4 * i + 0) * 64]);
            fma_row(a, v.y, &sWa[(4 * i + 1) * 64]);
            fma_row(a, v.z, &sWa[(4 * i + 2) * 64]);
            fma_row(a, v.w, &sWa[(4 * i + 3) * 64]);
        }
        float4* o = reinterpret_cast<float4*>(&g_t0[r * 64]);
#pragma unroll
        for (int jj = 0; jj < 16; jj++)
            o[jj] = make_float4(a[jj * 4 + 0], a[jj * 4 + 1], a[jj * 4 + 2], a[jj * 4 + 3]);
    }
    {
        float a[64];
#pragma unroll
        for (int j = 0; j < 64; j++) a[j] = sbb[j];
#pragma unroll 1
        for (int i = 0; i < 16; i++) {
            float4 v = xr4[i];
            fma_row(a, v.x, &sWb[(4 * i + 0) * 64]);
            fma_row(a, v.y, &sWb[(4 * i + 1) * 64]);
            fma_row(a, v.z, &sWb[(4 * i + 2) * 64]);
            fma_row(a, v.w, &sWb[(4 * i + 3) * 64]);
        }
        float4* o = reinterpret_cast<float4*>(&g_t1[r * 64]);
#pragma unroll
        for (int jj = 0; jj < 16; jj++)
            o[jj] = make_float4(a[jj * 4 + 0], a[jj * 4 + 1], a[jj * 4 + 2], a[jj * 4 + 3]);
    }
}

// ---------------- CSR build (per launch, deterministic inputs) --------------
__global__ void k_czero() {
    int i = blockIdx.x * blockDim.x + threadIdx.x;
    if (i < NN) g_cnt[i] = 0;
}
__global__ void k_hist(const int* __restrict__ dst) {
    int e = blockIdx.x * blockDim.x + threadIdx.x;
    if (e < EE) atomicAdd(&g_cnt[dst[e]], 1);
}
// single block of 1024 threads, 8 nodes each; exclusive scan -> rowptr + cursors
__global__ void k_scan() {
    __shared__ int sp[1024];
    int t = threadIdx.x;
    int base = t * 8;
    int loc[8];
    int sum = 0;
#pragma unroll
    for (int j = 0; j < 8; j++) { loc[j] = g_cnt[base + j]; sum += loc[j]; }
    sp[t] = sum;
    __syncthreads();
    for (int off = 1; off < 1024; off <<= 1) {
        int v = (t >= off) ? sp[t - off] : 0;
        __syncthreads();
        sp[t] += v;
        __syncthreads();
    }
    int run = sp[t] - sum;      // exclusive prefix of this thread's chunk
#pragma unroll
    for (int j = 0; j < 8; j++) {
        g_rp[base + j] = run;
        g_fill[base + j] = run;
        run += loc[j];
    }
    if (t == 1023) g_rp[NN] = run;
}
__global__ void k_scatter(const int* __restrict__ src, const int* __restrict__ dst) {
    int e = blockIdx.x * blockDim.x + threadIdx.x;
    if (e >= EE) return;
    int d = dst[e];
    int pos = atomicAdd(&g_fill[d], 1);
    g_cs[pos] = src[e];
    g_ce[pos] = e;
}

// ---------------- GAT edge pass 1: logits -> exp (store p only) -------------
__global__ void k_edge_att(const int* __restrict__ src, const int* __restrict__ dst,
                           const float* __restrict__ att) {
    __shared__ float satt[64];
    if (threadIdx.x < 64) satt[threadIdx.x] = att[threadIdx.x];
    __syncthreads();
    int e = blockIdx.x * blockDim.x + threadIdx.x;
    if (e >= ET) return;
    int s, d;
    if (e < EE) { s = src[e]; d = dst[e]; } else { s = e - EE; d = s; }

    const float4* xl = reinterpret_cast<const float4*>(&g_t0[s * 64]);
    const float4* xr = reinterpret_cast<const float4*>(&g_t1[d * 64]);
    float lg[4] = {0.f, 0.f, 0.f, 0.f};
#pragma unroll
    for (int i = 0; i < 16; i++) {
        float4 a = xl[i], b = xr[i];
        float v0 = a.x + b.x; v0 = v0 > 0.f ? v0 : 0.2f * v0;
        float v1 = a.y + b.y; v1 = v1 > 0.f ? v1 : 0.2f * v1;
        float v2 = a.z + b.z; v2 = v2 > 0.f ? v2 : 0.2f * v2;
        float v3 = a.w + b.w; v3 = v3 > 0.f ? v3 : 0.2f * v3;
        lg[i >> 2] += v0 * satt[i * 4 + 0] + v1 * satt[i * 4 + 1]
                    + v2 * satt[i * 4 + 2] + v3 * satt[i * 4 + 3];
    }
    float4 p = make_float4(expf(lg[0]), expf(lg[1]), expf(lg[2]), expf(lg[3]));
    *reinterpret_cast<float4*>(&g_p[e * 4]) = p;   // softmax shift-invariant
}

// ---------------- GAT pass 2: warp-per-dst CSR aggregation ------------------
// acc = sum_e p_e * xl[src_e];  den = sum_e p_e;  x[d] += acc/den + bo
__global__ void k_dst_agg(const float* __restrict__ bo) {
    int w = (blockIdx.x * blockDim.x + threadIdx.x) >> 5;   // dst node
    int lane = threadIdx.x & 31;
    if (w >= NN) return;
    int beg = g_rp[w], end = g_rp[w + 1];
    int hl = lane >> 4;            // head of channel `lane` (0/1); +2 for hi half

    float acc0 = 0.f, acc1 = 0.f, d0 = 0.f, d1 = 0.f;
    for (int k = beg; k < end; k++) {
        int s = g_cs[k];
        int e = g_ce[k];
        float plo = g_p[e * 4 + hl];
        float phi = g_p[e * 4 + 2 + hl];
        float a = g_t0[s * 64 + lane];
        float b = g_t0[s * 64 + 32 + lane];
        acc0 += plo * a; d0 += plo;
        acc1 += phi * b; d1 += phi;
    }
    { // self loop (edge id EE + w, src = w)
        int e = EE + w;
        float plo = g_p[e * 4 + hl];
        float phi = g_p[e * 4 + 2 + hl];
        acc0 += plo * g_t0[w * 64 + lane];        d0 += plo;
        acc1 += phi * g_t0[w * 64 + 32 + lane];   d1 += phi;
    }
    g_x[w * 64 + lane]      += acc0 / d0 + bo[lane];
    g_x[w * 64 + 32 + lane] += acc1 / d1 + bo[32 + lane];
}

// ---------------- edge MLP + scatter into dense NxN output ------------------
// h1 = A[src] + B[dst]; h2 = relu(h1 @ We2 + be2); v = sigmoid(h2 . We3 + be3)
// packed f32x2 FMAs: accumulators hold channel pairs (2j, 2j+1)
__global__ void k_edge_mlp(const int* __restrict__ src, const int* __restrict__ dst,
                           const float* __restrict__ We2, const float* __restrict__ be2,
                           const float* __restrict__ We3, const float* __restrict__ be3,
                           float* __restrict__ out) {
    __shared__ __align__(16) float sW[64 * 64];
    __shared__ float sb2[64], sw3[64];
    __shared__ float sb3;
    for (int i = threadIdx.x; i < 4096; i += blockDim.x) sW[i] = We2[i];
    if (threadIdx.x < 64) { sb2[threadIdx.x] = be2[threadIdx.x]; sw3[threadIdx.x] = We3[threadIdx.x]; }
    if (threadIdx.x == 0) sb3 = be3[0];
    __syncthreads();
    int e = blockIdx.x * blockDim.x + threadIdx.x;
    if (e >= EE) return;
    int s = src[e], d = dst[e];

    unsigned long long acc[32];
#pragma unroll
    for (int j = 0; j < 32; j++) acc[j] = pack2(sb2[2 * j], sb2[2 * j + 1]);

    const float4* A = reinterpret_cast<const float4*>(&g_t0[s * 64]);
    const float4* B = reinterpret_cast<const float4*>(&g_t1[d * 64]);
#pragma unroll 1
    for (int i = 0; i < 16; i++) {
        float4 av = A[i], bv = B[i];
        float vs[4] = {av.x + bv.x, av.y + bv.y, av.z + bv.z, av.w + bv.w};
#pragma unroll
        for (int q = 0; q < 4; q++) {
            unsigned long long vv = pack2(vs[q], vs[q]);
            const ulonglong2* w2 = reinterpret_cast<const ulonglong2*>(&sW[(4 * i + q) * 64]);
#pragma unroll
            for (int jj = 0; jj < 16; jj++) {
                ulonglong2 wp = w2[jj];
                fma2(acc[2 * jj + 0], vv, wp.x);
                fma2(acc[2 * jj + 1], vv, wp.y);
            }
        }
    }
    float t = sb3;
#pragma unroll
    for (int j = 0; j < 32; j++) {
        float lo, hi;
        unpack2(acc[j], lo, hi);
        t += fmaxf(lo, 0.f) * sw3[2 * j] + fmaxf(hi, 0.f) * sw3[2 * j + 1];
    }
    float v = 1.f / (1.f + expf(-t));
    out[(size_t)s * NN + d] = v;
}

// ---------------------------------------------------------------------------
extern "C" void kernel_launch(void* const* d_in, const int* in_sizes, int n_in,
                              void* d_out, int out_size) {
    const float* x    = (const float*)d_in[0];
    const float* W1   = (const float*)d_in[1];
    const float* b1   = (const float*)d_in[2];
    const float* W2   = (const float*)d_in[3];
    const float* b2   = (const float*)d_in[4];
    const float* Wl1  = (const float*)d_in[5];
    const float* bl1  = (const float*)d_in[6];
    const float* Wr1  = (const float*)d_in[7];
    const float* br1  = (const float*)d_in[8];
    const float* att1 = (const float*)d_in[9];
    const float* bo1  = (const float*)d_in[10];
    const float* W4   = (const float*)d_in[11];
    const float* b4   = (const float*)d_in[12];
    const float* Wl2  = (const float*)d_in[13];
    const float* bl2  = (const float*)d_in[14];
    const float* Wr2  = (const float*)d_in[15];
    const float* br2  = (const float*)d_in[16];
    const float* att2 = (const float*)d_in[17];
    const float* bo2  = (const float*)d_in[18];
    const float* W5   = (const float*)d_in[19];
    const float* b5   = (const float*)d_in[20];
    const float* We1  = (const float*)d_in[21];
    const float* be1  = (const float*)d_in[22];
    const float* We2  = (const float*)d_in[23];
    const float* be2  = (const float*)d_in[24];
    const float* We3  = (const float*)d_in[25];
    const float* be3  = (const float*)d_in[26];
    const int*   src  = (const int*)d_in[27];
    const int*   dst  = (const int*)d_in[28];
    float* out = (float*)d_out;

    const int NB128 = NN / 128;                  // node kernels: thread per row
    const int EB    = (ET + 255) / 256;          // edge blocks (incl self loops)
    const int EB0   = (EE + 255) / 256;          // edge blocks (no self loops)

    cudaMemsetAsync(d_out, 0, (size_t)NN * NN * sizeof(float));

    // CSR-by-dst build (independent of node pipeline)
    k_czero<<<NN / 256, 256>>>();
    k_hist<<<EB0, 256>>>(dst);
    k_scan<<<1, 1024>>>();
    k_scatter<<<EB0, 256>>>(src, dst);

    k_in_mlp<<<NB128, 128>>>(x, W1, b1);
    k_resid<<<NB128, 128>>>(W2, b2);

    // GAT layer 1
    k_lin2<<<NB128, 128>>>(Wl1, bl1, Wr1, br1);
    k_edge_att<<<EB, 256>>>(src, dst, att1);
    k_dst_agg<<<NN / 8, 256>>>(bo1);

    k_resid<<<NB128, 128>>>(W4, b4);

    // GAT layer 2
    k_lin2<<<NB128, 128>>>(Wl2, bl2, Wr2, br2);
    k_edge_att<<<EB, 256>>>(src, dst, att2);
    k_dst_agg<<<NN / 8, 256>>>(bo2);

    k_resid<<<NB128, 128>>>(W5, b5);

    // per-edge MLP: precompute per-node halves of the first linear layer
    k_lin2<<<NB128, 128>>>(We1, nullptr, We1 + 64 * 64, be1);
    k_edge_mlp<<<EB0, 256>>>(src, dst, We2, be2, We3, be3, out);
}